// round 14
// baseline (speedup 1.0000x reference)
#include <cuda_runtime.h>

// ---------------------------------------------------------------------------
// EnrichClassifier: block-sparse pathway MLP.
//   dims: x[8192,5000] -> h1[4000] -> h2[2000] -> h3[1000] -> scores[200] -> out[50]
//   Regular structure: every pathway has exactly 100 genes, l1=20, l2=10, l3=5.
//   Layers 2..4 are block-diagonal; only m1 (200 rows of it) must be read.
// ---------------------------------------------------------------------------

#define NG   5000   // genes
#define NB   8192   // batch
#define NP   200    // pathways
#define NKG  100    // genes per pathway
#define NL1  20     // layer-1 units per pathway
#define NL2  10
#define NL3  5
#define NH1  4000
#define NH2  2000
#define NH3  1000
#define NLBL 50

#define TGX  ((NG + 63) / 64)    // 79 transpose tiles along genes
#define TGY  (NB / 64)           // 128 transpose tiles along batch

typedef unsigned long long u64;

// ---- scratch (device globals: only allowed form of scratch) ----------------
__device__ __align__(16) float g_xT[(size_t)NG * NB];            // 163.84 MB transposed x
__device__ int   g_geneoff[NP * NKG];                            // gene * NB element offsets
__device__ __align__(16) float g_w1f[NP * NKG * NL1 * 2];        // BN-folded, DUPLICATED [p][s][j][2]
__device__ float g_b1f[NP * NL1];
__device__ __align__(16) float g_w2f[NP * NL1 * NL2 * 2];        // [p][t][j][2] duplicated pairs
__device__ float g_b2f[NP * NL2];
__device__ __align__(16) float g_w3f[NP * NL2 * NL3 * 2];        // [p][t][j][2]
__device__ float g_b3f[NP * NL3];
__device__ __align__(16) float g_w4f[NP * NL3 * 2];              // [p][t][2]
__device__ __align__(16) float g_scoresT[(size_t)NP * NB];       // [p][b]

// ---- packed f32x2 helpers ---------------------------------------------------
__device__ __forceinline__ u64 fma2(u64 a, u64 b, u64 c) {
    u64 d;
    asm("fma.rn.f32x2 %0, %1, %2, %3;" : "=l"(d) : "l"(a), "l"(b), "l"(c));
    return d;
}

__device__ __forceinline__ u64 pack2(float lo, float hi) {
    u64 r;
    asm("mov.b64 %0, {%1, %2};" : "=l"(r) : "f"(lo), "f"(hi));
    return r;
}

__device__ __forceinline__ void unpack2(u64 v, float& lo, float& hi) {
    asm("mov.b64 {%0, %1}, %2;" : "=f"(lo), "=f"(hi) : "l"(v));
}

__device__ __forceinline__ u64 bias_relu2(u64 v, float bias) {
    float a, b;
    unpack2(v, a, b);
    a = fmaxf(a + bias, 0.0f);
    b = fmaxf(b + bias, 0.0f);
    return pack2(a, b);
}

// ---------------------------------------------------------------------------
// K1 (fused prep + transpose): blocks [0, NP) do gene extraction + BN weight
// folding (one pathway each); blocks [NP, NP + TGX*TGY) transpose one 64x64
// tile of x.
// ---------------------------------------------------------------------------
__global__ void __launch_bounds__(256) prep_transpose_kernel(
    const float* __restrict__ x,
    const float* __restrict__ m1,
    const float* __restrict__ w1, const float* __restrict__ b1,
    const float* __restrict__ w2, const float* __restrict__ b2,
    const float* __restrict__ w3, const float* __restrict__ b3,
    const float* __restrict__ w4,
    const float* __restrict__ ga1, const float* __restrict__ be1,
    const float* __restrict__ rm1, const float* __restrict__ rv1,
    const float* __restrict__ ga2, const float* __restrict__ be2,
    const float* __restrict__ rm2, const float* __restrict__ rv2,
    const float* __restrict__ ga3, const float* __restrict__ be3,
    const float* __restrict__ rm3, const float* __restrict__ rv3) {
    const int tid = threadIdx.x;                 // 256 threads

    if (blockIdx.x < NP) {
        // ================= prep branch =================
        const int p = blockIdx.x;
        __shared__ int cnt[257];
        __shared__ int s_go[NKG];
        __shared__ float s1[NL1], s2[NL2], s3[NL3];

        const float* row = m1 + (size_t)(p * NL1) * NG;
        const int CH = (NG + 255) / 256;         // 20
        int start = tid * CH;
        int end = start + CH; if (end > NG) end = NG;
        if (start > NG) start = NG;

        int c = 0;
        for (int g = start; g < end; g++) c += (row[g] != 0.0f);
        cnt[tid + 1] = c;

        if (tid < NL1) {
            int u = p * NL1 + tid;
            float s = ga1[u] * rsqrtf(rv1[u] + 1e-5f);
            s1[tid] = s;
            g_b1f[u] = s * (b1[u] - rm1[u]) + be1[u];
        }
        if (tid < NL2) {
            int u = p * NL2 + tid;
            float s = ga2[u] * rsqrtf(rv2[u] + 1e-5f);
            s2[tid] = s;
            g_b2f[u] = s * (b2[u] - rm2[u]) + be2[u];
        }
        if (tid < NL3) {
            int u = p * NL3 + tid;
            float s = ga3[u] * rsqrtf(rv3[u] + 1e-5f);
            s3[tid] = s;
            g_b3f[u] = s * (b3[u] - rm3[u]) + be3[u];
        }
        __syncthreads();

        if (tid == 0) {
            cnt[0] = 0;
            for (int i = 1; i <= 256; i++) cnt[i] += cnt[i - 1];
        }
        __syncthreads();

        {
            int off = cnt[tid];
            for (int g = start; g < end; g++) {
                if (row[g] != 0.0f) {
                    s_go[off] = g * NB;
                    g_geneoff[p * NKG + off] = g * NB;
                    off++;
                }
            }
        }
        __syncthreads();

        // weight folding: layer-1 gather + fold, DUPLICATED pairs [p][s][j][2]
        for (int i = tid; i < NKG * NL1; i += 256) {
            int s = i / NL1, j = i - s * NL1;
            int gene = s_go[s] >> 13;            // / NB
            float v = w1[(size_t)(p * NL1 + j) * NG + gene] * s1[j];
            size_t o = ((size_t)p * NKG * NL1 + i) * 2;
            g_w1f[o] = v; g_w1f[o + 1] = v;
        }
        for (int i = tid; i < NL1 * NL2; i += 256) {
            int t = i / NL2, j = i - t * NL2;
            float v = w2[(size_t)(p * NL2 + j) * NH1 + p * NL1 + t] * s2[j];
            size_t o = (((size_t)p * NL1 + t) * NL2 + j) * 2;
            g_w2f[o] = v; g_w2f[o + 1] = v;
        }
        if (tid < NL2 * NL3) {
            int t = tid / NL3, j = tid - t * NL3;
            float v = w3[(size_t)(p * NL3 + j) * NH2 + p * NL2 + t] * s3[j];
            size_t o = (((size_t)p * NL2 + t) * NL3 + j) * 2;
            g_w3f[o] = v; g_w3f[o + 1] = v;
        }
        if (tid < NL3) {
            float v = w4[(size_t)p * NH3 + p * NL3 + tid];
            g_w4f[(p * NL3 + tid) * 2] = v;
            g_w4f[(p * NL3 + tid) * 2 + 1] = v;
        }
    } else {
        // ================= transpose branch =================
        __shared__ float tile[64][65];           // [gene_local][batch_local]
        const int t = blockIdx.x - NP;
        const int gx = (t % TGX) * 64;           // gene base
        const int by = (t / TGX) * 64;           // batch base
        const int tx = tid & 15;                 // float4 column
        const int ty = tid >> 4;                 // row group (16)

        #pragma unroll
        for (int r = 0; r < 4; r++) {
            int b = by + ty + r * 16;
            int g4 = gx + tx * 4;
            float4 v = (g4 < NG)
                ? *reinterpret_cast<const float4*>(x + (size_t)b * NG + g4)
                : make_float4(0.f, 0.f, 0.f, 0.f);
            int bl = ty + r * 16;
            tile[tx * 4 + 0][bl] = v.x;
            tile[tx * 4 + 1][bl] = v.y;
            tile[tx * 4 + 2][bl] = v.z;
            tile[tx * 4 + 3][bl] = v.w;
        }
        __syncthreads();
        #pragma unroll
        for (int r = 0; r < 4; r++) {
            int g = gx + ty + r * 16;
            if (g < NG) {
                int gl = ty + r * 16;
                float4 v = make_float4(tile[gl][tx * 4 + 0], tile[gl][tx * 4 + 1],
                                       tile[gl][tx * 4 + 2], tile[gl][tx * 4 + 3]);
                *reinterpret_cast<float4*>(g_xT + (size_t)g * NB + by + tx * 4) = v;
            }
        }
    }
}

// ---------------------------------------------------------------------------
// Tail: bias+relu on batch-packed h1, then layers 2..4, write float2 scores.
// ---------------------------------------------------------------------------
__device__ __forceinline__ void tail_chain(
    u64* __restrict__ h1,
    const float* __restrict__ s_b1,
    const u64* __restrict__ s_w2, const float* __restrict__ s_b2,
    const u64* __restrict__ s_w3, const float* __restrict__ s_b3,
    const u64* __restrict__ s_w4, float b4v,
    float* __restrict__ dst) {
    #pragma unroll
    for (int j = 0; j < NL1; j++) h1[j] = bias_relu2(h1[j], s_b1[j]);

    u64 h2[NL2];
    #pragma unroll
    for (int j = 0; j < NL2; j++) h2[j] = 0ULL;
    #pragma unroll
    for (int t = 0; t < NL1; t++) {
        #pragma unroll
        for (int j = 0; j < NL2; j++)
            h2[j] = fma2(h1[t], s_w2[t * NL2 + j], h2[j]);
    }
    #pragma unroll
    for (int j = 0; j < NL2; j++) h2[j] = bias_relu2(h2[j], s_b2[j]);

    u64 h3[NL3];
    #pragma unroll
    for (int j = 0; j < NL3; j++) h3[j] = 0ULL;
    #pragma unroll
    for (int t = 0; t < NL2; t++) {
        #pragma unroll
        for (int j = 0; j < NL3; j++)
            h3[j] = fma2(h2[t], s_w3[t * NL3 + j], h3[j]);
    }
    #pragma unroll
    for (int j = 0; j < NL3; j++) h3[j] = bias_relu2(h3[j], s_b3[j]);

    u64 sc = 0ULL;
    #pragma unroll
    for (int t = 0; t < NL3; t++) sc = fma2(h3[t], s_w4[t], sc);

    float sa, sb;
    unpack2(sc, sa, sb);
    sa = fmaxf(sa + b4v, 0.0f);
    sb = fmaxf(sb + b4v, 0.0f);
    *reinterpret_cast<float2*>(dst) = make_float2(sa, sb);
}

// ---------------------------------------------------------------------------
// K2: fused pathway chain, unit-split halves with NATIVE batch-pair f32x2.
// 256 threads, grid (200 pathways, 16 batch tiles of 512 rows).
// Thread pair (tid>>1) shares one x quad (LDG.128, rows bq..bq+3 = two
// natural f32x2 row-pairs, consumed DIRECTLY, no movs). half = tid&1 owns
// units [10*half, 10*half+10): accumulators acc[10][2] batch-packed (40 regs).
// Weights duplicated per unit, 2 units per ulonglong2 {wa,wa,wb,wb}:
//   per gene per thread: 1 LDG.128 + 5 LDS.128 + 20 fma.rn.f32x2 = 26 slots
//   (vs 34 incl. 8 movs in the R11 loop) and a shorter LDG->FMA chain.
// After layer 1: 10 shfl_xor(1) u64 (even thread keeps row-pair 0, odd keeps
// row-pair 1, each ends with all 20 units) — zero repack movs — then tail.
// ---------------------------------------------------------------------------
#define PF 3

__global__ void __launch_bounds__(256, 3) pathway_kernel(const float* __restrict__ b4) {
    const int p = blockIdx.x;
    const int tid = threadIdx.x;
    const int half = tid & 1;                    // unit half
    const int bq = blockIdx.y * 512 + (tid >> 1) * 4;   // batch quad base

    __shared__ ulonglong2 s_w1d[NKG * NL1 / 2];  // [gene][unit-pair] dup, 16 KB
    __shared__ u64 s_w2[NL1 * NL2];              // [t][j] dup pairs
    __shared__ u64 s_w3[NL2 * NL3];              // [t][j]
    __shared__ u64 s_w4[NL3];
    __shared__ int s_go[NKG];
    __shared__ float s_b1[NL1], s_b2[NL2], s_b3[NL3], s_b4;

    {
        const float4* src1 = reinterpret_cast<const float4*>(g_w1f + (size_t)p * NKG * NL1 * 2);
        float4* dst1 = reinterpret_cast<float4*>(s_w1d);
        for (int i = tid; i < NKG * NL1 * 2 / 4; i += 256) dst1[i] = src1[i];

        const float2* src2 = reinterpret_cast<const float2*>(g_w2f + (size_t)p * NL1 * NL2 * 2);
        float2* dst2 = reinterpret_cast<float2*>(s_w2);
        if (tid < NL1 * NL2) dst2[tid] = src2[tid];

        const float2* src3 = reinterpret_cast<const float2*>(g_w3f + (size_t)p * NL2 * NL3 * 2);
        float2* dst3 = reinterpret_cast<float2*>(s_w3);
        if (tid < NL2 * NL3) dst3[tid] = src3[tid];

        const float2* src4 = reinterpret_cast<const float2*>(g_w4f + (size_t)p * NL3 * 2);
        float2* dst4 = reinterpret_cast<float2*>(s_w4);
        if (tid < NL3) dst4[tid] = src4[tid];

        if (tid < NKG) s_go[tid] = g_geneoff[p * NKG + tid];
        if (tid < NL1) s_b1[tid] = g_b1f[p * NL1 + tid];
        if (tid < NL2) s_b2[tid] = g_b2f[p * NL2 + tid];
        if (tid < NL3) s_b3[tid] = g_b3f[p * NL3 + tid];
        if (tid == 0)  s_b4 = b4[p];
    }
    __syncthreads();

    // ---- layer 1: acc[j][rp] = local unit j (global 10*half+j), row-pair rp
    u64 acc[10][2];
    #pragma unroll
    for (int j = 0; j < 10; j++) { acc[j][0] = 0ULL; acc[j][1] = 0ULL; }

    const float* xb = g_xT + bq;
    // half's 5 unit-pair ulonglong2s start at [gene][half*5]
    const ulonglong2* w1b = s_w1d + half * 5;
    ulonglong2 xv0[PF], xv1[PF];

#define COMPUTE_GENE(xq, gidx)                                   \
    do {                                                         \
        const ulonglong2* wr_ = w1b + (gidx) * (NL1 / 2);        \
        _Pragma("unroll")                                        \
        for (int k_ = 0; k_ < 5; k_++) {                         \
            ulonglong2 w_ = wr_[k_];                             \
            acc[2 * k_][0]     = fma2((xq).x, w_.x, acc[2 * k_][0]);     \
            acc[2 * k_][1]     = fma2((xq).y, w_.x, acc[2 * k_][1]);     \
            acc[2 * k_ + 1][0] = fma2((xq).x, w_.y, acc[2 * k_ + 1][0]); \
            acc[2 * k_ + 1][1] = fma2((xq).y, w_.y, acc[2 * k_ + 1][1]); \
        }                                                        \
    } while (0)

    // prologue: load genes 0..PF-1 (x quad = 4 batch rows)
    #pragma unroll
    for (int u = 0; u < PF; u++)
        xv0[u] = *reinterpret_cast<const ulonglong2*>(xb + s_go[u]);

    // main loop: 16 iterations cover genes 0..95; prefetch reaches gene 98.
    #pragma unroll 1
    for (int c = 0; c < 96; c += 2 * PF) {
        #pragma unroll
        for (int u = 0; u < PF; u++)
            xv1[u] = *reinterpret_cast<const ulonglong2*>(xb + s_go[c + PF + u]);

        #pragma unroll
        for (int u = 0; u < PF; u++) COMPUTE_GENE(xv0[u], c + u);

        #pragma unroll
        for (int u = 0; u < PF; u++)
            xv0[u] = *reinterpret_cast<const ulonglong2*>(xb + s_go[c + 2 * PF + u]);

        #pragma unroll
        for (int u = 0; u < PF; u++) COMPUTE_GENE(xv1[u], c + PF + u);
    }

    // epilogue: xv0 holds genes 96..98; gene 99 loaded directly.
    {
        ulonglong2 xl = *reinterpret_cast<const ulonglong2*>(xb + s_go[99]);
        #pragma unroll
        for (int u = 0; u < PF; u++) COMPUTE_GENE(xv0[u], 96 + u);
        COMPUTE_GENE(xl, 99);
    }
#undef COMPUTE_GENE

    // ---- exchange with partner lane: even thread ends with row-pair 0 of
    //      all 20 units, odd with row-pair 1. Zero repack movs.
    u64 h1[NL1];
    #pragma unroll
    for (int j = 0; j < 10; j++) {
        u64 send = half ? acc[j][0] : acc[j][1];
        u64 recv = __shfl_xor_sync(0xffffffffu, send, 1);
        if (half) {
            h1[10 + j] = acc[j][1];
            h1[j]      = recv;
        } else {
            h1[j]      = acc[j][0];
            h1[10 + j] = recv;
        }
    }

    // ---- layers 2..4 ----
    float* dst = g_scoresT + (size_t)p * NB + bq + 2 * half;
    tail_chain(h1, s_b1, s_w2, s_b2, s_w3, s_b3, s_w4, s_b4, dst);
}

// ---------------------------------------------------------------------------
// K3: classifier: out[b,l] = sum_k scoresT[k][b] * wc[l,k] + bc[l]
// 8-way K split (25 k per octant) -> 256 blocks / 2048 warps; score reads
// are 8-lane broadcast; shfl-xor(1,2,4) reduction.
// ---------------------------------------------------------------------------
__global__ void __launch_bounds__(256) classifier_kernel(
    const float* __restrict__ wc, const float* __restrict__ bc,
    float* __restrict__ out) {
    __shared__ float s_wc[NLBL * NP];            // 40 KB
    const int tid = threadIdx.x;

    for (int i = tid; i < NLBL * NP; i += 256) s_wc[i] = wc[i];
    __syncthreads();

    const int gt = blockIdx.x * 256 + tid;
    const int b = gt >> 3;                       // batch row
    const int split = gt & 7;                    // k-octant
    const int k0 = split * (NP / 8);             // 25 k each

    float acc[NLBL];
    #pragma unroll
    for (int l = 0; l < NLBL; l++) acc[l] = 0.0f;

    const float* sp = g_scoresT + b;
    #pragma unroll 1
    for (int k = k0; k < k0 + NP / 8; k++) {
        float sv = sp[(size_t)k * NB];           // 8-lane broadcast per k-row
        #pragma unroll
        for (int l = 0; l < NLBL; l++) acc[l] = fmaf(sv, s_wc[l * NP + k], acc[l]);
    }

    #pragma unroll
    for (int l = 0; l < NLBL; l++) {
        float v = acc[l];
        v += __shfl_xor_sync(0xffffffffu, v, 1);
        v += __shfl_xor_sync(0xffffffffu, v, 2);
        v += __shfl_xor_sync(0xffffffffu, v, 4);
        acc[l] = v;
    }

    if (split == 0) {
        float* o = out + (size_t)b * NLBL;
        #pragma unroll
        for (int l = 0; l < NLBL; l++) o[l] = acc[l] + __ldg(bc + l);
    }
}

// ---------------------------------------------------------------------------
// launch
// ---------------------------------------------------------------------------
extern "C" void kernel_launch(void* const* d_in, const int* in_sizes, int n_in,
                              void* d_out, int out_size) {
    const float* x   = (const float*)d_in[0];
    const float* w1  = (const float*)d_in[1];
    const float* b1  = (const float*)d_in[2];
    const float* m1  = (const float*)d_in[3];
    const float* w2  = (const float*)d_in[4];
    const float* b2  = (const float*)d_in[5];
    // m2 = d_in[6]  (unused: block-diagonal by construction)
    const float* w3  = (const float*)d_in[7];
    const float* b3  = (const float*)d_in[8];
    // m3 = d_in[9]
    const float* w4  = (const float*)d_in[10];
    const float* b4  = (const float*)d_in[11];
    // m4 = d_in[12]
    const float* ga1 = (const float*)d_in[13];
    const float* be1 = (const float*)d_in[14];
    const float* rm1 = (const float*)d_in[15];
    const float* rv1 = (const float*)d_in[16];
    const float* ga2 = (const float*)d_in[17];
    const float* be2 = (const float*)d_in[18];
    const float* rm2 = (const float*)d_in[19];
    const float* rv2 = (const float*)d_in[20];
    const float* ga3 = (const float*)d_in[21];
    const float* be3 = (const float*)d_in[22];
    const float* rm3 = (const float*)d_in[23];
    const float* rv3 = (const float*)d_in[24];
    const float* wc  = (const float*)d_in[25];
    const float* bc  = (const float*)d_in[26];
    float* out = (float*)d_out;

    prep_transpose_kernel<<<NP + TGX * TGY, 256>>>(
        x, m1, w1, b1, w2, b2, w3, b3, w4,
        ga1, be1, rm1, rv1,
        ga2, be2, rm2, rv2,
        ga3, be3, rm3, rv3);
    pathway_kernel<<<dim3(NP, NB / 512), 256>>>(b4);
    classifier_kernel<<<NB * 8 / 256, 256>>>(wc, bc, out);
}

// round 15
// speedup vs baseline: 1.1317x; 1.1317x over previous
#include <cuda_runtime.h>

// ---------------------------------------------------------------------------
// EnrichClassifier: block-sparse pathway MLP.
//   dims: x[8192,5000] -> h1[4000] -> h2[2000] -> h3[1000] -> scores[200] -> out[50]
//   Regular structure: every pathway has exactly 100 genes, l1=20, l2=10, l3=5.
//   Layers 2..4 are block-diagonal; only m1 (200 rows of it) must be read.
// Best measured configuration (R11, 245.9us): unit-split pathway loop with
// non-duplicated LDS.64 weights, PF=3 double-buffered gather, 3 blocks/SM.
// ---------------------------------------------------------------------------

#define NG   5000   // genes
#define NB   8192   // batch
#define NP   200    // pathways
#define NKG  100    // genes per pathway
#define NL1  20     // layer-1 units per pathway
#define NL2  10
#define NL3  5
#define NH1  4000
#define NH2  2000
#define NH3  1000
#define NLBL 50

#define TGX  ((NG + 63) / 64)    // 79 transpose tiles along genes
#define TGY  (NB / 64)           // 128 transpose tiles along batch

typedef unsigned long long u64;

// ---- scratch (device globals: only allowed form of scratch) ----------------
__device__ __align__(16) float g_xT[(size_t)NG * NB];            // 163.84 MB transposed x
__device__ int   g_geneoff[NP * NKG];                            // gene * NB element offsets
__device__ __align__(16) float g_w1f[NP * NKG * NL1];            // BN-folded, NON-duplicated [p][s][j]
__device__ float g_b1f[NP * NL1];
__device__ __align__(16) float g_w2f[NP * NL1 * NL2 * 2];        // [p][t][j][2] duplicated pairs
__device__ float g_b2f[NP * NL2];
__device__ __align__(16) float g_w3f[NP * NL2 * NL3 * 2];        // [p][t][j][2]
__device__ float g_b3f[NP * NL3];
__device__ __align__(16) float g_w4f[NP * NL3 * 2];              // [p][t][2]
__device__ __align__(16) float g_scoresT[(size_t)NP * NB];       // [p][b]

// ---- packed f32x2 helpers ---------------------------------------------------
__device__ __forceinline__ u64 fma2(u64 a, u64 b, u64 c) {
    u64 d;
    asm("fma.rn.f32x2 %0, %1, %2, %3;" : "=l"(d) : "l"(a), "l"(b), "l"(c));
    return d;
}

__device__ __forceinline__ u64 pack2(float lo, float hi) {
    u64 r;
    asm("mov.b64 %0, {%1, %2};" : "=l"(r) : "f"(lo), "f"(hi));
    return r;
}

__device__ __forceinline__ void unpack2(u64 v, float& lo, float& hi) {
    asm("mov.b64 {%0, %1}, %2;" : "=f"(lo), "=f"(hi) : "l"(v));
}

__device__ __forceinline__ u64 bias_relu2(u64 v, float bias) {
    float a, b;
    unpack2(v, a, b);
    a = fmaxf(a + bias, 0.0f);
    b = fmaxf(b + bias, 0.0f);
    return pack2(a, b);
}

// ---------------------------------------------------------------------------
// K1 (fused prep + transpose): blocks [0, NP) do gene extraction + BN weight
// folding (one pathway each); blocks [NP, NP + TGX*TGY) transpose one 64x64
// tile of x. Independent work, one launch.
// ---------------------------------------------------------------------------
__global__ void __launch_bounds__(256) prep_transpose_kernel(
    const float* __restrict__ x,
    const float* __restrict__ m1,
    const float* __restrict__ w1, const float* __restrict__ b1,
    const float* __restrict__ w2, const float* __restrict__ b2,
    const float* __restrict__ w3, const float* __restrict__ b3,
    const float* __restrict__ w4,
    const float* __restrict__ ga1, const float* __restrict__ be1,
    const float* __restrict__ rm1, const float* __restrict__ rv1,
    const float* __restrict__ ga2, const float* __restrict__ be2,
    const float* __restrict__ rm2, const float* __restrict__ rv2,
    const float* __restrict__ ga3, const float* __restrict__ be3,
    const float* __restrict__ rm3, const float* __restrict__ rv3) {
    const int tid = threadIdx.x;                 // 256 threads

    if (blockIdx.x < NP) {
        // ================= prep branch =================
        const int p = blockIdx.x;
        __shared__ int cnt[257];
        __shared__ int s_go[NKG];
        __shared__ float s1[NL1], s2[NL2], s3[NL3];

        const float* row = m1 + (size_t)(p * NL1) * NG;
        const int CH = (NG + 255) / 256;         // 20
        int start = tid * CH;
        int end = start + CH; if (end > NG) end = NG;
        if (start > NG) start = NG;

        int c = 0;
        for (int g = start; g < end; g++) c += (row[g] != 0.0f);
        cnt[tid + 1] = c;

        if (tid < NL1) {
            int u = p * NL1 + tid;
            float s = ga1[u] * rsqrtf(rv1[u] + 1e-5f);
            s1[tid] = s;
            g_b1f[u] = s * (b1[u] - rm1[u]) + be1[u];
        }
        if (tid < NL2) {
            int u = p * NL2 + tid;
            float s = ga2[u] * rsqrtf(rv2[u] + 1e-5f);
            s2[tid] = s;
            g_b2f[u] = s * (b2[u] - rm2[u]) + be2[u];
        }
        if (tid < NL3) {
            int u = p * NL3 + tid;
            float s = ga3[u] * rsqrtf(rv3[u] + 1e-5f);
            s3[tid] = s;
            g_b3f[u] = s * (b3[u] - rm3[u]) + be3[u];
        }
        __syncthreads();

        if (tid == 0) {
            cnt[0] = 0;
            for (int i = 1; i <= 256; i++) cnt[i] += cnt[i - 1];
        }
        __syncthreads();

        {
            int off = cnt[tid];
            for (int g = start; g < end; g++) {
                if (row[g] != 0.0f) {
                    s_go[off] = g * NB;
                    g_geneoff[p * NKG + off] = g * NB;
                    off++;
                }
            }
        }
        __syncthreads();

        // weight folding
        for (int i = tid; i < NKG * NL1; i += 256) {
            int s = i / NL1, j = i - s * NL1;
            int gene = s_go[s] >> 13;            // / NB
            g_w1f[(size_t)p * NKG * NL1 + i] =
                w1[(size_t)(p * NL1 + j) * NG + gene] * s1[j];
        }
        for (int i = tid; i < NL1 * NL2; i += 256) {
            int t = i / NL2, j = i - t * NL2;
            float v = w2[(size_t)(p * NL2 + j) * NH1 + p * NL1 + t] * s2[j];
            size_t o = (((size_t)p * NL1 + t) * NL2 + j) * 2;
            g_w2f[o] = v; g_w2f[o + 1] = v;
        }
        if (tid < NL2 * NL3) {
            int t = tid / NL3, j = tid - t * NL3;
            float v = w3[(size_t)(p * NL3 + j) * NH2 + p * NL2 + t] * s3[j];
            size_t o = (((size_t)p * NL2 + t) * NL3 + j) * 2;
            g_w3f[o] = v; g_w3f[o + 1] = v;
        }
        if (tid < NL3) {
            float v = w4[(size_t)p * NH3 + p * NL3 + tid];
            g_w4f[(p * NL3 + tid) * 2] = v;
            g_w4f[(p * NL3 + tid) * 2 + 1] = v;
        }
    } else {
        // ================= transpose branch =================
        __shared__ float tile[64][65];           // [gene_local][batch_local]
        const int t = blockIdx.x - NP;
        const int gx = (t % TGX) * 64;           // gene base
        const int by = (t / TGX) * 64;           // batch base
        const int tx = tid & 15;                 // float4 column
        const int ty = tid >> 4;                 // row group (16)

        #pragma unroll
        for (int r = 0; r < 4; r++) {
            int b = by + ty + r * 16;
            int g4 = gx + tx * 4;
            float4 v = (g4 < NG)
                ? *reinterpret_cast<const float4*>(x + (size_t)b * NG + g4)
                : make_float4(0.f, 0.f, 0.f, 0.f);
            int bl = ty + r * 16;
            tile[tx * 4 + 0][bl] = v.x;
            tile[tx * 4 + 1][bl] = v.y;
            tile[tx * 4 + 2][bl] = v.z;
            tile[tx * 4 + 3][bl] = v.w;
        }
        __syncthreads();
        #pragma unroll
        for (int r = 0; r < 4; r++) {
            int g = gx + ty + r * 16;
            if (g < NG) {
                int gl = ty + r * 16;
                float4 v = make_float4(tile[gl][tx * 4 + 0], tile[gl][tx * 4 + 1],
                                       tile[gl][tx * 4 + 2], tile[gl][tx * 4 + 3]);
                *reinterpret_cast<float4*>(g_xT + (size_t)g * NB + by + tx * 4) = v;
            }
        }
    }
}

// ---------------------------------------------------------------------------
// Tail: bias+relu on batch-packed h1, then layers 2..4, write float2 scores.
// ---------------------------------------------------------------------------
__device__ __forceinline__ void tail_chain(
    u64* __restrict__ h1,
    const float* __restrict__ s_b1,
    const u64* __restrict__ s_w2, const float* __restrict__ s_b2,
    const u64* __restrict__ s_w3, const float* __restrict__ s_b3,
    const u64* __restrict__ s_w4, float b4v,
    float* __restrict__ dst) {
    #pragma unroll
    for (int j = 0; j < NL1; j++) h1[j] = bias_relu2(h1[j], s_b1[j]);

    u64 h2[NL2];
    #pragma unroll
    for (int j = 0; j < NL2; j++) h2[j] = 0ULL;
    #pragma unroll
    for (int t = 0; t < NL1; t++) {
        #pragma unroll
        for (int j = 0; j < NL2; j++)
            h2[j] = fma2(h1[t], s_w2[t * NL2 + j], h2[j]);
    }
    #pragma unroll
    for (int j = 0; j < NL2; j++) h2[j] = bias_relu2(h2[j], s_b2[j]);

    u64 h3[NL3];
    #pragma unroll
    for (int j = 0; j < NL3; j++) h3[j] = 0ULL;
    #pragma unroll
    for (int t = 0; t < NL2; t++) {
        #pragma unroll
        for (int j = 0; j < NL3; j++)
            h3[j] = fma2(h2[t], s_w3[t * NL3 + j], h3[j]);
    }
    #pragma unroll
    for (int j = 0; j < NL3; j++) h3[j] = bias_relu2(h3[j], s_b3[j]);

    u64 sc = 0ULL;
    #pragma unroll
    for (int t = 0; t < NL3; t++) sc = fma2(h3[t], s_w4[t], sc);

    float sa, sb;
    unpack2(sc, sa, sb);
    sa = fmaxf(sa + b4v, 0.0f);
    sb = fmaxf(sb + b4v, 0.0f);
    *reinterpret_cast<float2*>(dst) = make_float2(sa, sb);
}

// ---------------------------------------------------------------------------
// K2: fused pathway chain, unit-SPLIT across thread pairs, PF=3 pipelined
// gather (R11 configuration — best measured).
// ---------------------------------------------------------------------------
#define PF 3

__global__ void __launch_bounds__(256, 3) pathway_kernel(const float* __restrict__ b4) {
    const int p = blockIdx.x;
    const int tid = threadIdx.x;
    const int half = tid & 1;                    // unit half
    const int bq = blockIdx.y * 512 + (tid >> 1) * 4;   // batch quad base

    __shared__ u64 s_w1_64[NKG * NL1 / 2];       // [s][pair] 10 u64 per gene, 8 KB
    __shared__ u64 s_w2[NL1 * NL2];              // [t][j] dup pairs
    __shared__ u64 s_w3[NL2 * NL3];              // [t][j]
    __shared__ u64 s_w4[NL3];
    __shared__ int s_go[NKG];
    __shared__ float s_b1[NL1], s_b2[NL2], s_b3[NL3], s_b4;

    {
        const float4* src1 = reinterpret_cast<const float4*>(g_w1f + (size_t)p * NKG * NL1);
        float4* dst1 = reinterpret_cast<float4*>(s_w1_64);
        for (int i = tid; i < NKG * NL1 / 4; i += 256) dst1[i] = src1[i];

        const float2* src2 = reinterpret_cast<const float2*>(g_w2f + (size_t)p * NL1 * NL2 * 2);
        float2* dst2 = reinterpret_cast<float2*>(s_w2);
        if (tid < NL1 * NL2) dst2[tid] = src2[tid];

        const float2* src3 = reinterpret_cast<const float2*>(g_w3f + (size_t)p * NL2 * NL3 * 2);
        float2* dst3 = reinterpret_cast<float2*>(s_w3);
        if (tid < NL2 * NL3) dst3[tid] = src3[tid];

        const float2* src4 = reinterpret_cast<const float2*>(g_w4f + (size_t)p * NL3 * 2);
        float2* dst4 = reinterpret_cast<float2*>(s_w4);
        if (tid < NL3) dst4[tid] = src4[tid];

        if (tid < NKG) s_go[tid] = g_geneoff[p * NKG + tid];
        if (tid < NL1) s_b1[tid] = g_b1f[p * NL1 + tid];
        if (tid < NL2) s_b2[tid] = g_b2f[p * NL2 + tid];
        if (tid < NL3) s_b3[tid] = g_b3f[p * NL3 + tid];
        if (tid == 0)  s_b4 = b4[p];
    }
    __syncthreads();

    // ---- layer 1: acc[k][r] = unit-pair (5*half+k), batch row (bq+r) ----
    u64 acc[5][4];
    #pragma unroll
    for (int k = 0; k < 5; k++)
        #pragma unroll
        for (int r = 0; r < 4; r++) acc[k][r] = 0ULL;

    const float* xb = g_xT + bq;
    const u64* w1b = s_w1_64 + half * 5;
    ulonglong2 xv0[PF], xv1[PF];

#define COMPUTE_GENE(xq, gidx)                                   \
    do {                                                         \
        float x0_, x1_, x2_, x3_;                                \
        unpack2((xq).x, x0_, x1_);                               \
        unpack2((xq).y, x2_, x3_);                               \
        u64 xd0_ = pack2(x0_, x0_), xd1_ = pack2(x1_, x1_);      \
        u64 xd2_ = pack2(x2_, x2_), xd3_ = pack2(x3_, x3_);      \
        const u64* wr_ = w1b + (gidx) * (NL1 / 2);               \
        _Pragma("unroll")                                        \
        for (int k_ = 0; k_ < 5; k_++) {                         \
            u64 w_ = wr_[k_];                                    \
            acc[k_][0] = fma2(xd0_, w_, acc[k_][0]);             \
            acc[k_][1] = fma2(xd1_, w_, acc[k_][1]);             \
            acc[k_][2] = fma2(xd2_, w_, acc[k_][2]);             \
            acc[k_][3] = fma2(xd3_, w_, acc[k_][3]);             \
        }                                                        \
    } while (0)

    // prologue: load genes 0..PF-1 (x quad = 4 batch rows)
    #pragma unroll
    for (int u = 0; u < PF; u++)
        xv0[u] = *reinterpret_cast<const ulonglong2*>(xb + s_go[u]);

    // main loop: 16 iterations cover genes 0..95; prefetch reaches gene 98.
    #pragma unroll 1
    for (int c = 0; c < 96; c += 2 * PF) {
        #pragma unroll
        for (int u = 0; u < PF; u++)
            xv1[u] = *reinterpret_cast<const ulonglong2*>(xb + s_go[c + PF + u]);

        #pragma unroll
        for (int u = 0; u < PF; u++) COMPUTE_GENE(xv0[u], c + u);

        #pragma unroll
        for (int u = 0; u < PF; u++)
            xv0[u] = *reinterpret_cast<const ulonglong2*>(xb + s_go[c + 2 * PF + u]);

        #pragma unroll
        for (int u = 0; u < PF; u++) COMPUTE_GENE(xv1[u], c + PF + u);
    }

    // epilogue: xv0 holds genes 96..98; gene 99 loaded directly.
    {
        ulonglong2 xl = *reinterpret_cast<const ulonglong2*>(xb + s_go[99]);
        #pragma unroll
        for (int u = 0; u < PF; u++) COMPUTE_GENE(xv0[u], 96 + u);
        COMPUTE_GENE(xl, 99);
    }
#undef COMPUTE_GENE

    // ---- exchange with partner lane ----
    u64 other[5][2];
    #pragma unroll
    for (int k = 0; k < 5; k++) {
        #pragma unroll
        for (int r = 0; r < 2; r++) {
            u64 send = half ? acc[k][r] : acc[k][2 + r];
            other[k][r] = __shfl_xor_sync(0xffffffffu, send, 1);
        }
    }

    u64 p04[5][2], p59[5][2];
    #pragma unroll
    for (int k = 0; k < 5; k++) {
        u64 own0 = half ? acc[k][2] : acc[k][0];
        u64 own1 = half ? acc[k][3] : acc[k][1];
        p04[k][0] = half ? other[k][0] : own0;
        p04[k][1] = half ? other[k][1] : own1;
        p59[k][0] = half ? own0 : other[k][0];
        p59[k][1] = half ? own1 : other[k][1];
    }

    // repack to batch-pairs h1[j] = {rowA_j, rowB_j}
    u64 h1[NL1];
    #pragma unroll
    for (int k = 0; k < 5; k++) {
        float a0, a1, b0, b1;
        unpack2(p04[k][0], a0, a1);
        unpack2(p04[k][1], b0, b1);
        h1[2 * k]     = pack2(a0, b0);
        h1[2 * k + 1] = pack2(a1, b1);
        float c0, c1, d0, d1;
        unpack2(p59[k][0], c0, c1);
        unpack2(p59[k][1], d0, d1);
        h1[10 + 2 * k]     = pack2(c0, d0);
        h1[10 + 2 * k + 1] = pack2(c1, d1);
    }

    // ---- layers 2..4 ----
    float* dst = g_scoresT + (size_t)p * NB + bq + 2 * half;
    tail_chain(h1, s_b1, s_w2, s_b2, s_w3, s_b3, s_w4, s_b4, dst);
}

// ---------------------------------------------------------------------------
// K3: classifier: out[b,l] = sum_k scoresT[k][b] * wc[l,k] + bc[l]
// 8-way K split (25 k per octant) -> 256 blocks / 2048 warps; score reads
// are 8-lane broadcast; shfl-xor(1,2,4) reduction.
// ---------------------------------------------------------------------------
__global__ void __launch_bounds__(256) classifier_kernel(
    const float* __restrict__ wc, const float* __restrict__ bc,
    float* __restrict__ out) {
    __shared__ float s_wc[NLBL * NP];            // 40 KB
    const int tid = threadIdx.x;

    for (int i = tid; i < NLBL * NP; i += 256) s_wc[i] = wc[i];
    __syncthreads();

    const int gt = blockIdx.x * 256 + tid;
    const int b = gt >> 3;                       // batch row
    const int split = gt & 7;                    // k-octant
    const int k0 = split * (NP / 8);             // 25 k each

    float acc[NLBL];
    #pragma unroll
    for (int l = 0; l < NLBL; l++) acc[l] = 0.0f;

    const float* sp = g_scoresT + b;
    #pragma unroll 1
    for (int k = k0; k < k0 + NP / 8; k++) {
        float sv = sp[(size_t)k * NB];           // 8-lane broadcast per k-row
        #pragma unroll
        for (int l = 0; l < NLBL; l++) acc[l] = fmaf(sv, s_wc[l * NP + k], acc[l]);
    }

    #pragma unroll
    for (int l = 0; l < NLBL; l++) {
        float v = acc[l];
        v += __shfl_xor_sync(0xffffffffu, v, 1);
        v += __shfl_xor_sync(0xffffffffu, v, 2);
        v += __shfl_xor_sync(0xffffffffu, v, 4);
        acc[l] = v;
    }

    if (split == 0) {
        float* o = out + (size_t)b * NLBL;
        #pragma unroll
        for (int l = 0; l < NLBL; l++) o[l] = acc[l] + __ldg(bc + l);
    }
}

// ---------------------------------------------------------------------------
// launch
// ---------------------------------------------------------------------------
extern "C" void kernel_launch(void* const* d_in, const int* in_sizes, int n_in,
                              void* d_out, int out_size) {
    const float* x   = (const float*)d_in[0];
    const float* w1  = (const float*)d_in[1];
    const float* b1  = (const float*)d_in[2];
    const float* m1  = (const float*)d_in[3];
    const float* w2  = (const float*)d_in[4];
    const float* b2  = (const float*)d_in[5];
    // m2 = d_in[6]  (unused: block-diagonal by construction)
    const float* w3  = (const float*)d_in[7];
    const float* b3  = (const float*)d_in[8];
    // m3 = d_in[9]
    const float* w4  = (const float*)d_in[10];
    const float* b4  = (const float*)d_in[11];
    // m4 = d_in[12]
    const float* ga1 = (const float*)d_in[13];
    const float* be1 = (const float*)d_in[14];
    const float* rm1 = (const float*)d_in[15];
    const float* rv1 = (const float*)d_in[16];
    const float* ga2 = (const float*)d_in[17];
    const float* be2 = (const float*)d_in[18];
    const float* rm2 = (const float*)d_in[19];
    const float* rv2 = (const float*)d_in[20];
    const float* ga3 = (const float*)d_in[21];
    const float* be3 = (const float*)d_in[22];
    const float* rm3 = (const float*)d_in[23];
    const float* rv3 = (const float*)d_in[24];
    const float* wc  = (const float*)d_in[25];
    const float* bc  = (const float*)d_in[26];
    float* out = (float*)d_out;

    prep_transpose_kernel<<<NP + TGX * TGY, 256>>>(
        x, m1, w1, b1, w2, b2, w3, b3, w4,
        ga1, be1, rm1, rv1,
        ga2, be2, rm2, rv2,
        ga3, be3, rm3, rv3);
    pathway_kernel<<<dim3(NP, NB / 512), 256>>>(b4);
    classifier_kernel<<<NB * 8 / 256, 256>>>(wc, bc, out);
}

// round 16
// speedup vs baseline: 1.1897x; 1.0512x over previous
#include <cuda_runtime.h>

// ---------------------------------------------------------------------------
// EnrichClassifier: block-sparse pathway MLP.
//   dims: x[8192,5000] -> h1[4000] -> h2[2000] -> h3[1000] -> scores[200] -> out[50]
//   Regular structure: every pathway has exactly 100 genes, l1=20, l2=10, l3=5.
//   Layers 2..4 are block-diagonal; only m1 (200 rows of it) must be read.
// R16: R11 inner loop unchanged; pathway blocks halved (128 thr, 6/SM) to cut
// wave-tail quantization; classifier k-loop unrolled x5 for gather MLP.
// ---------------------------------------------------------------------------

#define NG   5000   // genes
#define NB   8192   // batch
#define NP   200    // pathways
#define NKG  100    // genes per pathway
#define NL1  20     // layer-1 units per pathway
#define NL2  10
#define NL3  5
#define NH1  4000
#define NH2  2000
#define NH3  1000
#define NLBL 50

#define TGX  ((NG + 63) / 64)    // 79 transpose tiles along genes
#define TGY  (NB / 64)           // 128 transpose tiles along batch

typedef unsigned long long u64;

// ---- scratch (device globals: only allowed form of scratch) ----------------
__device__ __align__(16) float g_xT[(size_t)NG * NB];            // 163.84 MB transposed x
__device__ int   g_geneoff[NP * NKG];                            // gene * NB element offsets
__device__ __align__(16) float g_w1f[NP * NKG * NL1];            // BN-folded, NON-duplicated [p][s][j]
__device__ float g_b1f[NP * NL1];
__device__ __align__(16) float g_w2f[NP * NL1 * NL2 * 2];        // [p][t][j][2] duplicated pairs
__device__ float g_b2f[NP * NL2];
__device__ __align__(16) float g_w3f[NP * NL2 * NL3 * 2];        // [p][t][j][2]
__device__ float g_b3f[NP * NL3];
__device__ __align__(16) float g_w4f[NP * NL3 * 2];              // [p][t][2]
__device__ __align__(16) float g_scoresT[(size_t)NP * NB];       // [p][b]

// ---- packed f32x2 helpers ---------------------------------------------------
__device__ __forceinline__ u64 fma2(u64 a, u64 b, u64 c) {
    u64 d;
    asm("fma.rn.f32x2 %0, %1, %2, %3;" : "=l"(d) : "l"(a), "l"(b), "l"(c));
    return d;
}

__device__ __forceinline__ u64 pack2(float lo, float hi) {
    u64 r;
    asm("mov.b64 %0, {%1, %2};" : "=l"(r) : "f"(lo), "f"(hi));
    return r;
}

__device__ __forceinline__ void unpack2(u64 v, float& lo, float& hi) {
    asm("mov.b64 {%0, %1}, %2;" : "=f"(lo), "=f"(hi) : "l"(v));
}

__device__ __forceinline__ u64 bias_relu2(u64 v, float bias) {
    float a, b;
    unpack2(v, a, b);
    a = fmaxf(a + bias, 0.0f);
    b = fmaxf(b + bias, 0.0f);
    return pack2(a, b);
}

// ---------------------------------------------------------------------------
// K1 (fused prep + transpose): blocks [0, NP) do gene extraction + BN weight
// folding (one pathway each); blocks [NP, NP + TGX*TGY) transpose one 64x64
// tile of x. Independent work, one launch.
// ---------------------------------------------------------------------------
__global__ void __launch_bounds__(256) prep_transpose_kernel(
    const float* __restrict__ x,
    const float* __restrict__ m1,
    const float* __restrict__ w1, const float* __restrict__ b1,
    const float* __restrict__ w2, const float* __restrict__ b2,
    const float* __restrict__ w3, const float* __restrict__ b3,
    const float* __restrict__ w4,
    const float* __restrict__ ga1, const float* __restrict__ be1,
    const float* __restrict__ rm1, const float* __restrict__ rv1,
    const float* __restrict__ ga2, const float* __restrict__ be2,
    const float* __restrict__ rm2, const float* __restrict__ rv2,
    const float* __restrict__ ga3, const float* __restrict__ be3,
    const float* __restrict__ rm3, const float* __restrict__ rv3) {
    const int tid = threadIdx.x;                 // 256 threads

    if (blockIdx.x < NP) {
        // ================= prep branch =================
        const int p = blockIdx.x;
        __shared__ int cnt[257];
        __shared__ int s_go[NKG];
        __shared__ float s1[NL1], s2[NL2], s3[NL3];

        const float* row = m1 + (size_t)(p * NL1) * NG;
        const int CH = (NG + 255) / 256;         // 20
        int start = tid * CH;
        int end = start + CH; if (end > NG) end = NG;
        if (start > NG) start = NG;

        int c = 0;
        for (int g = start; g < end; g++) c += (row[g] != 0.0f);
        cnt[tid + 1] = c;

        if (tid < NL1) {
            int u = p * NL1 + tid;
            float s = ga1[u] * rsqrtf(rv1[u] + 1e-5f);
            s1[tid] = s;
            g_b1f[u] = s * (b1[u] - rm1[u]) + be1[u];
        }
        if (tid < NL2) {
            int u = p * NL2 + tid;
            float s = ga2[u] * rsqrtf(rv2[u] + 1e-5f);
            s2[tid] = s;
            g_b2f[u] = s * (b2[u] - rm2[u]) + be2[u];
        }
        if (tid < NL3) {
            int u = p * NL3 + tid;
            float s = ga3[u] * rsqrtf(rv3[u] + 1e-5f);
            s3[tid] = s;
            g_b3f[u] = s * (b3[u] - rm3[u]) + be3[u];
        }
        __syncthreads();

        if (tid == 0) {
            cnt[0] = 0;
            for (int i = 1; i <= 256; i++) cnt[i] += cnt[i - 1];
        }
        __syncthreads();

        {
            int off = cnt[tid];
            for (int g = start; g < end; g++) {
                if (row[g] != 0.0f) {
                    s_go[off] = g * NB;
                    g_geneoff[p * NKG + off] = g * NB;
                    off++;
                }
            }
        }
        __syncthreads();

        // weight folding
        for (int i = tid; i < NKG * NL1; i += 256) {
            int s = i / NL1, j = i - s * NL1;
            int gene = s_go[s] >> 13;            // / NB
            g_w1f[(size_t)p * NKG * NL1 + i] =
                w1[(size_t)(p * NL1 + j) * NG + gene] * s1[j];
        }
        for (int i = tid; i < NL1 * NL2; i += 256) {
            int t = i / NL2, j = i - t * NL2;
            float v = w2[(size_t)(p * NL2 + j) * NH1 + p * NL1 + t] * s2[j];
            size_t o = (((size_t)p * NL1 + t) * NL2 + j) * 2;
            g_w2f[o] = v; g_w2f[o + 1] = v;
        }
        if (tid < NL2 * NL3) {
            int t = tid / NL3, j = tid - t * NL3;
            float v = w3[(size_t)(p * NL3 + j) * NH2 + p * NL2 + t] * s3[j];
            size_t o = (((size_t)p * NL2 + t) * NL3 + j) * 2;
            g_w3f[o] = v; g_w3f[o + 1] = v;
        }
        if (tid < NL3) {
            float v = w4[(size_t)p * NH3 + p * NL3 + tid];
            g_w4f[(p * NL3 + tid) * 2] = v;
            g_w4f[(p * NL3 + tid) * 2 + 1] = v;
        }
    } else {
        // ================= transpose branch =================
        __shared__ float tile[64][65];           // [gene_local][batch_local]
        const int t = blockIdx.x - NP;
        const int gx = (t % TGX) * 64;           // gene base
        const int by = (t / TGX) * 64;           // batch base
        const int tx = tid & 15;                 // float4 column
        const int ty = tid >> 4;                 // row group (16)

        #pragma unroll
        for (int r = 0; r < 4; r++) {
            int b = by + ty + r * 16;
            int g4 = gx + tx * 4;
            float4 v = (g4 < NG)
                ? *reinterpret_cast<const float4*>(x + (size_t)b * NG + g4)
                : make_float4(0.f, 0.f, 0.f, 0.f);
            int bl = ty + r * 16;
            tile[tx * 4 + 0][bl] = v.x;
            tile[tx * 4 + 1][bl] = v.y;
            tile[tx * 4 + 2][bl] = v.z;
            tile[tx * 4 + 3][bl] = v.w;
        }
        __syncthreads();
        #pragma unroll
        for (int r = 0; r < 4; r++) {
            int g = gx + ty + r * 16;
            if (g < NG) {
                int gl = ty + r * 16;
                float4 v = make_float4(tile[gl][tx * 4 + 0], tile[gl][tx * 4 + 1],
                                       tile[gl][tx * 4 + 2], tile[gl][tx * 4 + 3]);
                *reinterpret_cast<float4*>(g_xT + (size_t)g * NB + by + tx * 4) = v;
            }
        }
    }
}

// ---------------------------------------------------------------------------
// Tail: bias+relu on batch-packed h1, then layers 2..4, write float2 scores.
// ---------------------------------------------------------------------------
__device__ __forceinline__ void tail_chain(
    u64* __restrict__ h1,
    const float* __restrict__ s_b1,
    const u64* __restrict__ s_w2, const float* __restrict__ s_b2,
    const u64* __restrict__ s_w3, const float* __restrict__ s_b3,
    const u64* __restrict__ s_w4, float b4v,
    float* __restrict__ dst) {
    #pragma unroll
    for (int j = 0; j < NL1; j++) h1[j] = bias_relu2(h1[j], s_b1[j]);

    u64 h2[NL2];
    #pragma unroll
    for (int j = 0; j < NL2; j++) h2[j] = 0ULL;
    #pragma unroll
    for (int t = 0; t < NL1; t++) {
        #pragma unroll
        for (int j = 0; j < NL2; j++)
            h2[j] = fma2(h1[t], s_w2[t * NL2 + j], h2[j]);
    }
    #pragma unroll
    for (int j = 0; j < NL2; j++) h2[j] = bias_relu2(h2[j], s_b2[j]);

    u64 h3[NL3];
    #pragma unroll
    for (int j = 0; j < NL3; j++) h3[j] = 0ULL;
    #pragma unroll
    for (int t = 0; t < NL2; t++) {
        #pragma unroll
        for (int j = 0; j < NL3; j++)
            h3[j] = fma2(h2[t], s_w3[t * NL3 + j], h3[j]);
    }
    #pragma unroll
    for (int j = 0; j < NL3; j++) h3[j] = bias_relu2(h3[j], s_b3[j]);

    u64 sc = 0ULL;
    #pragma unroll
    for (int t = 0; t < NL3; t++) sc = fma2(h3[t], s_w4[t], sc);

    float sa, sb;
    unpack2(sc, sa, sb);
    sa = fmaxf(sa + b4v, 0.0f);
    sb = fmaxf(sb + b4v, 0.0f);
    *reinterpret_cast<float2*>(dst) = make_float2(sa, sb);
}

// ---------------------------------------------------------------------------
// K2: fused pathway chain, unit-SPLIT across thread pairs, PF=3 pipelined
// gather. R16: 128-thread blocks at 6 blocks/SM (same 24 warps/SM, same
// 85-reg cap, same per-thread code) -> half the block duration, half the
// wave-tail quantization loss. Grid (200 pathways, 32 batch tiles of 256).
// ---------------------------------------------------------------------------
#define PF 3

__global__ void __launch_bounds__(128, 6) pathway_kernel(const float* __restrict__ b4) {
    const int p = blockIdx.x;
    const int tid = threadIdx.x;                 // 128 threads
    const int half = tid & 1;                    // unit half
    const int bq = blockIdx.y * 256 + (tid >> 1) * 4;   // batch quad base

    __shared__ u64 s_w1_64[NKG * NL1 / 2];       // [s][pair] 10 u64 per gene, 8 KB
    __shared__ u64 s_w2[NL1 * NL2];              // [t][j] dup pairs
    __shared__ u64 s_w3[NL2 * NL3];              // [t][j]
    __shared__ u64 s_w4[NL3];
    __shared__ int s_go[NKG];
    __shared__ float s_b1[NL1], s_b2[NL2], s_b3[NL3], s_b4;

    {
        const float4* src1 = reinterpret_cast<const float4*>(g_w1f + (size_t)p * NKG * NL1);
        float4* dst1 = reinterpret_cast<float4*>(s_w1_64);
        for (int i = tid; i < NKG * NL1 / 4; i += 128) dst1[i] = src1[i];

        const float2* src2 = reinterpret_cast<const float2*>(g_w2f + (size_t)p * NL1 * NL2 * 2);
        float2* dst2 = reinterpret_cast<float2*>(s_w2);
        for (int i = tid; i < NL1 * NL2; i += 128) dst2[i] = src2[i];

        const float2* src3 = reinterpret_cast<const float2*>(g_w3f + (size_t)p * NL2 * NL3 * 2);
        float2* dst3 = reinterpret_cast<float2*>(s_w3);
        if (tid < NL2 * NL3) dst3[tid] = src3[tid];

        const float2* src4 = reinterpret_cast<const float2*>(g_w4f + (size_t)p * NL3 * 2);
        float2* dst4 = reinterpret_cast<float2*>(s_w4);
        if (tid < NL3) dst4[tid] = src4[tid];

        if (tid < NKG) s_go[tid] = g_geneoff[p * NKG + tid];
        if (tid < NL1) s_b1[tid] = g_b1f[p * NL1 + tid];
        if (tid < NL2) s_b2[tid] = g_b2f[p * NL2 + tid];
        if (tid < NL3) s_b3[tid] = g_b3f[p * NL3 + tid];
        if (tid == 0)  s_b4 = b4[p];
    }
    __syncthreads();

    // ---- layer 1: acc[k][r] = unit-pair (5*half+k), batch row (bq+r) ----
    u64 acc[5][4];
    #pragma unroll
    for (int k = 0; k < 5; k++)
        #pragma unroll
        for (int r = 0; r < 4; r++) acc[k][r] = 0ULL;

    const float* xb = g_xT + bq;
    const u64* w1b = s_w1_64 + half * 5;
    ulonglong2 xv0[PF], xv1[PF];

#define COMPUTE_GENE(xq, gidx)                                   \
    do {                                                         \
        float x0_, x1_, x2_, x3_;                                \
        unpack2((xq).x, x0_, x1_);                               \
        unpack2((xq).y, x2_, x3_);                               \
        u64 xd0_ = pack2(x0_, x0_), xd1_ = pack2(x1_, x1_);      \
        u64 xd2_ = pack2(x2_, x2_), xd3_ = pack2(x3_, x3_);      \
        const u64* wr_ = w1b + (gidx) * (NL1 / 2);               \
        _Pragma("unroll")                                        \
        for (int k_ = 0; k_ < 5; k_++) {                         \
            u64 w_ = wr_[k_];                                    \
            acc[k_][0] = fma2(xd0_, w_, acc[k_][0]);             \
            acc[k_][1] = fma2(xd1_, w_, acc[k_][1]);             \
            acc[k_][2] = fma2(xd2_, w_, acc[k_][2]);             \
            acc[k_][3] = fma2(xd3_, w_, acc[k_][3]);             \
        }                                                        \
    } while (0)

    // prologue: load genes 0..PF-1 (x quad = 4 batch rows)
    #pragma unroll
    for (int u = 0; u < PF; u++)
        xv0[u] = *reinterpret_cast<const ulonglong2*>(xb + s_go[u]);

    // main loop: 16 iterations cover genes 0..95; prefetch reaches gene 98.
    #pragma unroll 1
    for (int c = 0; c < 96; c += 2 * PF) {
        #pragma unroll
        for (int u = 0; u < PF; u++)
            xv1[u] = *reinterpret_cast<const ulonglong2*>(xb + s_go[c + PF + u]);

        #pragma unroll
        for (int u = 0; u < PF; u++) COMPUTE_GENE(xv0[u], c + u);

        #pragma unroll
        for (int u = 0; u < PF; u++)
            xv0[u] = *reinterpret_cast<const ulonglong2*>(xb + s_go[c + 2 * PF + u]);

        #pragma unroll
        for (int u = 0; u < PF; u++) COMPUTE_GENE(xv1[u], c + PF + u);
    }

    // epilogue: xv0 holds genes 96..98; gene 99 loaded directly.
    {
        ulonglong2 xl = *reinterpret_cast<const ulonglong2*>(xb + s_go[99]);
        #pragma unroll
        for (int u = 0; u < PF; u++) COMPUTE_GENE(xv0[u], 96 + u);
        COMPUTE_GENE(xl, 99);
    }
#undef COMPUTE_GENE

    // ---- exchange with partner lane ----
    u64 other[5][2];
    #pragma unroll
    for (int k = 0; k < 5; k++) {
        #pragma unroll
        for (int r = 0; r < 2; r++) {
            u64 send = half ? acc[k][r] : acc[k][2 + r];
            other[k][r] = __shfl_xor_sync(0xffffffffu, send, 1);
        }
    }

    u64 p04[5][2], p59[5][2];
    #pragma unroll
    for (int k = 0; k < 5; k++) {
        u64 own0 = half ? acc[k][2] : acc[k][0];
        u64 own1 = half ? acc[k][3] : acc[k][1];
        p04[k][0] = half ? other[k][0] : own0;
        p04[k][1] = half ? other[k][1] : own1;
        p59[k][0] = half ? own0 : other[k][0];
        p59[k][1] = half ? own1 : other[k][1];
    }

    // repack to batch-pairs h1[j] = {rowA_j, rowB_j}
    u64 h1[NL1];
    #pragma unroll
    for (int k = 0; k < 5; k++) {
        float a0, a1, b0, b1;
        unpack2(p04[k][0], a0, a1);
        unpack2(p04[k][1], b0, b1);
        h1[2 * k]     = pack2(a0, b0);
        h1[2 * k + 1] = pack2(a1, b1);
        float c0, c1, d0, d1;
        unpack2(p59[k][0], c0, c1);
        unpack2(p59[k][1], d0, d1);
        h1[10 + 2 * k]     = pack2(c0, d0);
        h1[10 + 2 * k + 1] = pack2(c1, d1);
    }

    // ---- layers 2..4 ----
    float* dst = g_scoresT + (size_t)p * NB + bq + 2 * half;
    tail_chain(h1, s_b1, s_w2, s_b2, s_w3, s_b3, s_w4, s_b4, dst);
}

// ---------------------------------------------------------------------------
// K3: classifier: out[b,l] = sum_k scoresT[k][b] * wc[l,k] + bc[l]
// 8-way K split (25 k per octant); R16: k-loop unrolled x5 so the 5 L2
// broadcast loads issue back-to-back (MLP=5) before the 250-FMA block.
// ---------------------------------------------------------------------------
__global__ void __launch_bounds__(256) classifier_kernel(
    const float* __restrict__ wc, const float* __restrict__ bc,
    float* __restrict__ out) {
    __shared__ float s_wc[NLBL * NP];            // 40 KB
    const int tid = threadIdx.x;

    for (int i = tid; i < NLBL * NP; i += 256) s_wc[i] = wc[i];
    __syncthreads();

    const int gt = blockIdx.x * 256 + tid;
    const int b = gt >> 3;                       // batch row
    const int split = gt & 7;                    // k-octant
    const int k0 = split * (NP / 8);             // 25 k each

    float acc[NLBL];
    #pragma unroll
    for (int l = 0; l < NLBL; l++) acc[l] = 0.0f;

    const float* sp = g_scoresT + b;
    #pragma unroll 1
    for (int kk = k0; kk < k0 + NP / 8; kk += 5) {
        float sv[5];
        #pragma unroll
        for (int u = 0; u < 5; u++)
            sv[u] = sp[(size_t)(kk + u) * NB];   // 5 independent broadcast LDGs
        #pragma unroll
        for (int u = 0; u < 5; u++) {
            #pragma unroll
            for (int l = 0; l < NLBL; l++)
                acc[l] = fmaf(sv[u], s_wc[l * NP + kk + u], acc[l]);
        }
    }

    #pragma unroll
    for (int l = 0; l < NLBL; l++) {
        float v = acc[l];
        v += __shfl_xor_sync(0xffffffffu, v, 1);
        v += __shfl_xor_sync(0xffffffffu, v, 2);
        v += __shfl_xor_sync(0xffffffffu, v, 4);
        acc[l] = v;
    }

    if (split == 0) {
        float* o = out + (size_t)b * NLBL;
        #pragma unroll
        for (int l = 0; l < NLBL; l++) o[l] = acc[l] + __ldg(bc + l);
    }
}

// ---------------------------------------------------------------------------
// launch
// ---------------------------------------------------------------------------
extern "C" void kernel_launch(void* const* d_in, const int* in_sizes, int n_in,
                              void* d_out, int out_size) {
    const float* x   = (const float*)d_in[0];
    const float* w1  = (const float*)d_in[1];
    const float* b1  = (const float*)d_in[2];
    const float* m1  = (const float*)d_in[3];
    const float* w2  = (const float*)d_in[4];
    const float* b2  = (const float*)d_in[5];
    // m2 = d_in[6]  (unused: block-diagonal by construction)
    const float* w3  = (const float*)d_in[7];
    const float* b3  = (const float*)d_in[8];
    // m3 = d_in[9]
    const float* w4  = (const float*)d_in[10];
    const float* b4  = (const float*)d_in[11];
    // m4 = d_in[12]
    const float* ga1 = (const float*)d_in[13];
    const float* be1 = (const float*)d_in[14];
    const float* rm1 = (const float*)d_in[15];
    const float* rv1 = (const float*)d_in[16];
    const float* ga2 = (const float*)d_in[17];
    const float* be2 = (const float*)d_in[18];
    const float* rm2 = (const float*)d_in[19];
    const float* rv2 = (const float*)d_in[20];
    const float* ga3 = (const float*)d_in[21];
    const float* be3 = (const float*)d_in[22];
    const float* rm3 = (const float*)d_in[23];
    const float* rv3 = (const float*)d_in[24];
    const float* wc  = (const float*)d_in[25];
    const float* bc  = (const float*)d_in[26];
    float* out = (float*)d_out;

    prep_transpose_kernel<<<NP + TGX * TGY, 256>>>(
        x, m1, w1, b1, w2, b2, w3, b3, w4,
        ga1, be1, rm1, rv1,
        ga2, be2, rm2, rv2,
        ga3, be3, rm3, rv3);
    pathway_kernel<<<dim3(NP, NB / 256), 128>>>(b4);
    classifier_kernel<<<NB * 8 / 256, 256>>>(wc, bc, out);
}